// round 13
// baseline (speedup 1.0000x reference)
#include <cuda_runtime.h>
#include <cuda_bf16.h>
#include <math.h>

typedef unsigned long long ull;
typedef unsigned int u32;

#define DI __device__ __forceinline__

DI u32 pkbf(float a, float b){ u32 r; asm("cvt.rn.bf16x2.f32 %0, %1, %2;" : "=r"(r) : "f"(b), "f"(a)); return r; }  // mem order [a,b]
DI float bfres(float v){ __nv_bfloat16 h = __float2bfloat16(v); return v - __bfloat162float(h); }
DI u32 s2u(const void* p){ return (u32)__cvta_generic_to_shared(p); }

// warp mma: D[16x8] += A[16x16,row] * B[16x8,col], bf16 in, fp32 accum
DI void mma16816(float* d, const u32* a, u32 b0, u32 b1){
    asm volatile("mma.sync.aligned.m16n8k16.row.col.f32.bf16.bf16.f32 "
        "{%0,%1,%2,%3},{%4,%5,%6,%7},{%8,%9},{%0,%1,%2,%3};"
        : "+f"(d[0]), "+f"(d[1]), "+f"(d[2]), "+f"(d[3])
        : "r"(a[0]), "r"(a[1]), "r"(a[2]), "r"(a[3]), "r"(b0), "r"(b1));
}
DI void ldm_x4(u32 addr, u32* r){
    asm volatile("ldmatrix.sync.aligned.m8n8.x4.shared.b16 {%0,%1,%2,%3}, [%4];"
        : "=r"(r[0]), "=r"(r[1]), "=r"(r[2]), "=r"(r[3]) : "r"(addr));
}

static constexpr int B    = 32;
static constexpr int L    = 128;
static constexpr int H    = 1024;
static constexpr int EN   = 256;
static constexpr int ET   = 512;
static constexpr int EIN  = 768;
static constexpr int EIN2 = 1792;   // EIN + H
static constexpr int G4   = 4096;
static constexpr int VOUT = 50003;
static constexpr int LOGN = VOUT + L;
static constexpr int F3   = 3072;
static constexpr int NLOG = B * LOGN;
static constexpr int NCHUNK = 49;

// ---------------- scratch ----------------
__device__ __align__(16) float g_featT[F3 * B];
__device__ __align__(16) float g_gates[G4 * B];
__device__ __align__(16) float g_qT[H * B];
__device__ __align__(16) float g_scores[B * L];
__device__ float g_lse[B];
__device__ __align__(16) float g_context[B * H];
__device__ float g_sB[B];
__device__ __align__(16) float g_wgout[(VOUT + 64) * B];
__device__ float g_pmax[NCHUNK * 32];
__device__ float g_psum[NCHUNK * 32];
__device__ float g_wlse[B];
__device__ __align__(16) __nv_bfloat16 g_fhi[B * F3];
__device__ __align__(16) __nv_bfloat16 g_flo[B * F3];
__device__ __align__(16) __nv_bfloat16 g_ehi[B * L * H];
__device__ __align__(16) __nv_bfloat16 g_elo[B * L * H];
__device__ __align__(16) __nv_bfloat16 g_wmhi[H * H];
__device__ __align__(16) __nv_bfloat16 g_wmlo[H * H];
__device__ __align__(16) __nv_bfloat16 g_xbhi[B * EIN2];
__device__ __align__(16) __nv_bfloat16 g_xblo[B * EIN2];
__device__ __align__(16) __nv_bfloat16 g_hnhi[B * H];
__device__ __align__(16) __nv_bfloat16 g_hnlo[B * H];

// ---------------- K0: generic fp32 -> bf16 hi/lo split ----------------
__global__ void k0_split(const float* __restrict__ src, __nv_bfloat16* __restrict__ hi,
                         __nv_bfloat16* __restrict__ lo) {
    int i = blockIdx.x * 256 + threadIdx.x;
    float v = src[i];
    __nv_bfloat16 h = __float2bfloat16(v);
    hi[i] = h;
    lo[i] = __float2bfloat16(v - __bfloat162float(h));
}

// ---------------- K1: embeddings + staging + bias inits + x split ----------------
__global__ void k1_prep(const int* __restrict__ n_in, const int* __restrict__ t_in,
                        const float* __restrict__ h0, const float* __restrict__ h_parent,
                        const float* __restrict__ embN, const float* __restrict__ embT,
                        const float* __restrict__ v_b,
                        const float* __restrict__ b_ih, const float* __restrict__ b_hh,
                        const float* __restrict__ Wh_b) {
    int b = blockIdx.x;
    int t = threadIdx.x;
    int n  = n_in[b];
    int tt = t_in[b];
    for (int k = t; k < EIN; k += blockDim.x) {
        float v = (k < EN) ? embN[n * EN + k] : embT[(size_t)tt * ET + (k - EN)];
        __nv_bfloat16 h = __float2bfloat16(v);
        g_xbhi[b * EIN2 + k] = h;
        g_xblo[b * EIN2 + k] = __float2bfloat16(v - __bfloat162float(h));
    }
    for (int k = t; k < H; k += blockDim.x) {
        float v = h0[b * H + k];
        __nv_bfloat16 h = __float2bfloat16(v);
        g_xbhi[b * EIN2 + EIN + k] = h;
        g_xblo[b * EIN2 + EIN + k] = __float2bfloat16(v - __bfloat162float(h));
        g_featT[(2 * H + k) * B + b] = h_parent[b * H + k];
        g_qT[k * B + b] = Wh_b[k];
    }
    for (int j = t; j < G4; j += blockDim.x)
        g_gates[j * B + b] = b_ih[j] + b_hh[j];
    if (t < L) g_scores[b * L + t] = v_b[0];
}

// ---------------- KG: generic weight GEMM via mma, split-K, atomic out ----------------
static constexpr int GLDK = 40;
__global__ void __launch_bounds__(256) kg_mma(const float* __restrict__ A1, int ldA1, int kb1,
                                              const float* __restrict__ A2, int ldA2,
                                              const __nv_bfloat16* __restrict__ bhi,
                                              const __nv_bfloat16* __restrict__ blo, int ldB,
                                              float* __restrict__ out, int chunksPerSplit) {
    __shared__ __align__(16) __nv_bfloat16 sAhi[128 * GLDK];
    __shared__ __align__(16) __nv_bfloat16 sAlo[128 * GLDK];
    __shared__ __align__(16) __nv_bfloat16 sBhi[32 * GLDK];
    __shared__ __align__(16) __nv_bfloat16 sBlo[32 * GLDK];
    int tid = threadIdx.x, w = tid >> 5, lane = tid & 31;
    int g = lane >> 2, q = lane & 3;
    int r0 = blockIdx.x * 128;
    int c0 = blockIdx.y * chunksPerSplit;
    int nkt = chunksPerSplit;

    float d[4][4];
#pragma unroll
    for (int nb = 0; nb < 4; nb++)
#pragma unroll
        for (int c = 0; c < 4; c++) d[nb][c] = 0.f;

    float4 av[2][4];
    uint2 bh[2], bl[2];
    int arow = tid >> 3, ac4 = tid & 7;
    int bn = tid >> 3, bcc = tid & 7;

    // ldmatrix addressing
    u32 uAh = s2u(sAhi) + ((w * 16 + (lane & 15)) * GLDK + (lane >> 4) * 8) * 2;
    u32 uAl = uAh + (s2u(sAlo) - s2u(sAhi));
    u32 uBh = s2u(sBhi) + lane * GLDK * 2;
    u32 uBl = uBh + (s2u(sBlo) - s2u(sBhi));

    auto ldg = [&](int ch, int buf) {
        const float* A; int ld_; int kk;
        if (ch < kb1) { A = A1; ld_ = ldA1; kk = ch * 32; }
        else          { A = A2; ld_ = ldA2; kk = (ch - kb1) * 32; }
#pragma unroll
        for (int i = 0; i < 4; i++)
            av[buf][i] = *(const float4*)&A[(size_t)(r0 + arow + i * 32) * ld_ + kk + 4 * ac4];
        int kb = ch * 32;
        bh[buf] = *(const uint2*)&bhi[bn * ldB + kb + bcc * 4];
        bl[buf] = *(const uint2*)&blo[bn * ldB + kb + bcc * 4];
    };
    auto sts = [&](int buf) {
#pragma unroll
        for (int i = 0; i < 4; i++) {
            uint2 h, l;
            h.x = pkbf(av[buf][i].x, av[buf][i].y);
            h.y = pkbf(av[buf][i].z, av[buf][i].w);
            l.x = pkbf(bfres(av[buf][i].x), bfres(av[buf][i].y));
            l.y = pkbf(bfres(av[buf][i].z), bfres(av[buf][i].w));
            *(uint2*)&sAhi[(arow + i * 32) * GLDK + ac4 * 4] = h;
            *(uint2*)&sAlo[(arow + i * 32) * GLDK + ac4 * 4] = l;
        }
        *(uint2*)&sBhi[bn * GLDK + bcc * 4] = bh[buf];
        *(uint2*)&sBlo[bn * GLDK + bcc * 4] = bl[buf];
    };
    auto comp = [&]() {
#pragma unroll
        for (int ks = 0; ks < 2; ks++) {
            u32 ah[4], al[4], bh0v[4], bh1v[4], bl0v[4], bl1v[4];
            ldm_x4(uAh + ks * 32, ah);
            ldm_x4(uAl + ks * 32, al);
            ldm_x4(uBh + ks * 32, bh0v);
            ldm_x4(uBh + ks * 32 + 16, bh1v);
            ldm_x4(uBl + ks * 32, bl0v);
            ldm_x4(uBl + ks * 32 + 16, bl1v);
#pragma unroll
            for (int nb = 0; nb < 4; nb++) {
                mma16816(d[nb], ah, bh0v[nb], bh1v[nb]);
                mma16816(d[nb], al, bh0v[nb], bh1v[nb]);
                mma16816(d[nb], ah, bl0v[nb], bl1v[nb]);
            }
        }
    };

    ldg(c0, 0);
    if (nkt > 1) ldg(c0 + 1, 1);
    for (int t = 0; t < nkt; t++) {
        __syncthreads();
        sts(t & 1);
        if (t + 2 < nkt) ldg(c0 + t + 2, t & 1);
        __syncthreads();
        comp();
    }

    int vlo = r0 + w * 16 + g;
    int vhi = vlo + 8;
#pragma unroll
    for (int nb = 0; nb < 4; nb++) {
        int col = nb * 8 + q * 2;
        atomicAdd(&out[(size_t)vlo * 32 + col], d[nb][0]);
        atomicAdd(&out[(size_t)vlo * 32 + col + 1], d[nb][1]);
        atomicAdd(&out[(size_t)vhi * 32 + col], d[nb][2]);
        atomicAdd(&out[(size_t)vhi * 32 + col + 1], d[nb][3]);
    }
}

// ---------------- K3: LSTM pointwise (+ h_new bf16 split) ----------------
__global__ void k3_lstm(const float* __restrict__ c0, float* __restrict__ d_out) {
    int idx = blockIdx.x * blockDim.x + threadIdx.x;
    int b = idx & 31, j = idx >> 5;
    float gi = g_gates[j * B + b];
    float gf = g_gates[(H + j) * B + b];
    float gg = g_gates[(2 * H + j) * B + b];
    float go = g_gates[(3 * H + j) * B + b];
    float cp = c0[b * H + j];
    float si = 1.f / (1.f + expf(-gi));
    float sf = 1.f / (1.f + expf(-gf));
    float so = 1.f / (1.f + expf(-go));
    float cn = sf * cp + si * tanhf(gg);
    float hn = so * tanhf(cn);
    g_featT[(H + j) * B + b] = hn;
    __nv_bfloat16 hh = __float2bfloat16(hn);
    g_hnhi[b * H + j] = hh;
    g_hnlo[b * H + j] = __float2bfloat16(hn - __bfloat162float(hh));
    d_out[NLOG + b * H + j] = hn;
    d_out[NLOG + B * H + b * H + j] = cn;
}

// ---------------- K5: attention GEMM via mma 3-pass + fused v*tanh (ldmatrix) ----------------
static constexpr int K5KC  = 32;
static constexpr int K5LDK = 40;

__global__ void __launch_bounds__(256) k5_mma(const __nv_bfloat16* __restrict__ ehi,
                                              const __nv_bfloat16* __restrict__ elo,
                                              const __nv_bfloat16* __restrict__ wmhi,
                                              const __nv_bfloat16* __restrict__ wmlo,
                                              const float* __restrict__ Wm_b,
                                              const float* __restrict__ v_w) {
    __shared__ __align__(16) __nv_bfloat16 sAhi[128 * K5LDK];
    __shared__ __align__(16) __nv_bfloat16 sAlo[128 * K5LDK];
    __shared__ __align__(16) __nv_bfloat16 sBhi[64 * K5LDK];
    __shared__ __align__(16) __nv_bfloat16 sBlo[64 * K5LDK];
    __shared__ float red[128];
    int tid = threadIdx.x, w = tid >> 5, lane = tid & 31;
    int g = lane >> 2, q = lane & 3;
    int n0 = blockIdx.x * 64;
    int by = blockIdx.y;
    const __nv_bfloat16* Ah = ehi + (size_t)by * L * H;
    const __nv_bfloat16* Al = elo + (size_t)by * L * H;

    float d[8][4];
#pragma unroll
    for (int nb = 0; nb < 8; nb++)
#pragma unroll
        for (int c = 0; c < 4; c++) d[nb][c] = 0.f;

    uint4 avh[2], avl[2], bvh, bvl;
    int arow = tid >> 2, ac8 = (tid & 3) * 8;
    int brow = tid >> 2, bc8 = (tid & 3) * 8;

    u32 uAh = s2u(sAhi) + ((w * 16 + (lane & 15)) * K5LDK + (lane >> 4) * 8) * 2;
    u32 uAl = uAh + (s2u(sAlo) - s2u(sAhi));
    u32 uBh = s2u(sBhi) + lane * K5LDK * 2;
    u32 uBl = uBh + (s2u(sBlo) - s2u(sBhi));
    u32 bgrp = 32 * K5LDK * 2;   // second n-group offset

    auto ldg = [&](int ch) {
        int k0 = ch * K5KC;
#pragma unroll
        for (int i = 0; i < 2; i++) {
            avh[i] = *(const uint4*)&Ah[(arow + i * 64) * H + k0 + ac8];
            avl[i] = *(const uint4*)&Al[(arow + i * 64) * H + k0 + ac8];
        }
        bvh = *(const uint4*)&wmhi[(size_t)(n0 + brow) * H + k0 + bc8];
        bvl = *(const uint4*)&wmlo[(size_t)(n0 + brow) * H + k0 + bc8];
    };
    auto sts = [&]() {
#pragma unroll
        for (int i = 0; i < 2; i++) {
            *(uint4*)&sAhi[(arow + i * 64) * K5LDK + ac8] = avh[i];
            *(uint4*)&sAlo[(arow + i * 64) * K5LDK + ac8] = avl[i];
        }
        *(uint4*)&sBhi[brow * K5LDK + bc8] = bvh;
        *(uint4*)&sBlo[brow * K5LDK + bc8] = bvl;
    };
    auto comp = [&]() {
#pragma unroll
        for (int ks = 0; ks < 2; ks++) {
            u32 ah[4], al[4];
            u32 b0v[8], b1v[8], c0v[8], c1v[8];
            ldm_x4(uAh + ks * 32, ah);
            ldm_x4(uAl + ks * 32, al);
            ldm_x4(uBh + ks * 32, b0v);
            ldm_x4(uBh + bgrp + ks * 32, b0v + 4);
            ldm_x4(uBh + ks * 32 + 16, b1v);
            ldm_x4(uBh + bgrp + ks * 32 + 16, b1v + 4);
            ldm_x4(uBl + ks * 32, c0v);
            ldm_x4(uBl + bgrp + ks * 32, c0v + 4);
            ldm_x4(uBl + ks * 32 + 16, c1v);
            ldm_x4(uBl + bgrp + ks * 32 + 16, c1v + 4);
#pragma unroll
            for (int nb = 0; nb < 8; nb++) {
                mma16816(d[nb], ah, b0v[nb], b1v[nb]);
                mma16816(d[nb], al, b0v[nb], b1v[nb]);
                mma16816(d[nb], ah, c0v[nb], c1v[nb]);
            }
        }
    };

    constexpr int NCH = H / K5KC;
    ldg(0);
    for (int ch = 0; ch < NCH; ch++) {
        __syncthreads();
        sts();
        if (ch + 1 < NCH) ldg(ch + 1);
        __syncthreads();
        comp();
    }

    float plo = 0.f, phi = 0.f;
#pragma unroll
    for (int nb = 0; nb < 8; nb++) {
        int col0 = n0 + nb * 8 + q * 2;
        int col1 = col0 + 1;
        float vw0 = v_w[col0], vw1 = v_w[col1];
        float mb0 = Wm_b[col0], mb1 = Wm_b[col1];
        float q0 = g_qT[col0 * B + by];
        float q1 = g_qT[col1 * B + by];
        plo += vw0 * tanhf(d[nb][0] + mb0 + q0) + vw1 * tanhf(d[nb][1] + mb1 + q1);
        phi += vw0 * tanhf(d[nb][2] + mb0 + q0) + vw1 * tanhf(d[nb][3] + mb1 + q1);
    }
    plo += __shfl_xor_sync(~0u, plo, 1);
    plo += __shfl_xor_sync(~0u, plo, 2);
    phi += __shfl_xor_sync(~0u, phi, 1);
    phi += __shfl_xor_sync(~0u, phi, 2);
    if (q == 0) {
        red[w * 16 + g] = plo;
        red[w * 16 + g + 8] = phi;
    }
    __syncthreads();
    if (tid < 128) atomicAdd(&g_scores[by * L + tid], red[tid]);
}

// ---------------- K7: softmax over L + context ----------------
__global__ void k7_ctx(const float* __restrict__ enc, const unsigned char* __restrict__ mask) {
    __shared__ float sc[128];
    __shared__ float redm[16];
    int b = blockIdx.x, t = threadIdx.x;
    if (t < 128) {
        float s = g_scores[b * L + t];
        if (mask[b * L + t]) s = -1e20f;
        sc[t] = s;
        g_scores[b * L + t] = s;
    }
    __syncthreads();
    float m = (t < 128) ? sc[t] : -INFINITY;
#pragma unroll
    for (int o = 16; o > 0; o >>= 1) m = fmaxf(m, __shfl_xor_sync(~0u, m, o));
    if ((t & 31) == 0) redm[t >> 5] = m;
    __syncthreads();
    if (t == 0) {
        float mm = redm[0];
        for (int w = 1; w < 8; w++) mm = fmaxf(mm, redm[w]);
        redm[0] = mm;
    }
    __syncthreads();
    float mx = redm[0];
    float e = (t < 128) ? expf(sc[t] - mx) : 0.f;
    float s = e;
#pragma unroll
    for (int o = 16; o > 0; o >>= 1) s += __shfl_xor_sync(~0u, s, o);
    if ((t & 31) == 0) redm[8 + (t >> 5)] = s;
    __syncthreads();
    if (t == 0) {
        float ss = 0.f;
        for (int w = 0; w < 8; w++) ss += redm[8 + w];
        redm[8] = ss;
    }
    __syncthreads();
    float sum = redm[8];
    if (t < 128) sc[t] = e / sum;
    if (t == 0) g_lse[b] = mx + logf(sum);
    __syncthreads();
    const float* E = enc + (size_t)b * L * H;
#pragma unroll
    for (int jj = 0; jj < 4; jj++) {
        int j = t + jj * 256;
        float a = 0.f;
#pragma unroll 4
        for (int l = 0; l < 128; l++) a += sc[l] * E[l * H + j];
        g_context[b * H + j] = a;
        g_featT[j * B + b] = a;
    }
}

// ---------------- K8: pointer switch + copy-logits ----------------
__global__ void k8_s(const float* __restrict__ ws_w, const float* __restrict__ ws_b,
                     float* __restrict__ d_out) {
    __shared__ float red[8];
    __shared__ float sh[2];
    int b = blockIdx.x, t = threadIdx.x;
    float a = 0.f;
    for (int j = t; j < H; j += 256) a += g_context[b * H + j] * ws_w[j];
    for (int j = t; j < H; j += 256) a += g_featT[(H + j) * B + b] * ws_w[H + j];
#pragma unroll
    for (int o = 16; o > 0; o >>= 1) a += __shfl_xor_sync(~0u, a, o);
    if ((t & 31) == 0) red[t >> 5] = a;
    __syncthreads();
    if (t == 0) {
        float zz = ws_b[0];
        for (int w = 0; w < 8; w++) zz += red[w];
        float s  = (zz >= 0.f) ? -log1pf(expf(-zz)) : zz - log1pf(expf(zz));
        float zm = -zz;
        float l1 = (zm >= 0.f) ? -log1pf(expf(-zm)) : zm - log1pf(expf(zm));
        l1 = fmaxf(l1, -41.446531673892822f);
        g_sB[b] = s;
        sh[0] = l1;
        sh[1] = g_lse[b];
    }
    __syncthreads();
    if (t < 128)
        d_out[(size_t)b * LOGN + VOUT + t] = sh[0] + g_scores[b * L + t] - sh[1];
}

// ---------------- K9: split featT region into bf16 hi/lo, [b][k] layout ----------------
__global__ void k9_split(__nv_bfloat16* __restrict__ fhi, __nv_bfloat16* __restrict__ flo,
                         int koff) {
    int b = blockIdx.y;
    int k = koff + blockIdx.x * 256 + threadIdx.x;
    float v = g_featT[k * B + b];
    __nv_bfloat16 h = __float2bfloat16(v);
    fhi[b * F3 + k] = h;
    flo[b * F3 + k] = __float2bfloat16(v - __bfloat162float(h));
}

// ---------------- K10: vocab GEMM via mma 3-pass, KC=32, ldmatrix fragments ----------------
static constexpr int KC   = 32;
static constexpr int LDK  = 40;

template<bool FIRST>
__global__ void __launch_bounds__(256) k10_mma(const float* __restrict__ wg_w,
                                               const float* __restrict__ wg_b,
                                               const __nv_bfloat16* __restrict__ fhi,
                                               const __nv_bfloat16* __restrict__ flo,
                                               int ch0, int nch) {
    __shared__ __align__(16) __nv_bfloat16 sAhi[128 * LDK];
    __shared__ __align__(16) __nv_bfloat16 sAlo[128 * LDK];
    __shared__ __align__(16) __nv_bfloat16 sBhi[32 * LDK];
    __shared__ __align__(16) __nv_bfloat16 sBlo[32 * LDK];
    int tid = threadIdx.x, w = tid >> 5, lane = tid & 31;
    int r0 = blockIdx.x * 128;
    int g = lane >> 2, q = lane & 3;

    float d[4][4];
#pragma unroll
    for (int nb = 0; nb < 4; nb++)
#pragma unroll
        for (int c = 0; c < 4; c++) d[nb][c] = 0.f;

    float4 av[2][4];
    uint2 bh[2], bl[2];
    int arow = tid >> 3, ac4 = tid & 7;
    int bn = tid >> 3, bcc = tid & 7;

    u32 uAh = s2u(sAhi) + ((w * 16 + (lane & 15)) * LDK + (lane >> 4) * 8) * 2;
    u32 uAl = uAh + (s2u(sAlo) - s2u(sAhi));
    u32 uBh = s2u(sBhi) + lane * LDK * 2;
    u32 uBl = uBh + (s2u(sBlo) - s2u(sBhi));

    auto ldg = [&](int ch, int buf) {
        int k0 = ch * KC;
#pragma unroll
        for (int i = 0; i < 4; i++) {
            int rr = r0 + arow + i * 32;
            if (rr > VOUT - 1) rr = VOUT - 1;
            av[buf][i] = *(const float4*)&wg_w[(size_t)rr * F3 + k0 + 4 * ac4];
        }
        bh[buf] = *(const uint2*)&fhi[bn * F3 + k0 + bcc * 4];
        bl[buf] = *(const uint2*)&flo[bn * F3 + k0 + bcc * 4];
    };
    auto sts = [&](int buf) {
#pragma unroll
        for (int i = 0; i < 4; i++) {
            uint2 h, l;
            h.x = pkbf(av[buf][i].x, av[buf][i].y);
            h.y = pkbf(av[buf][i].z, av[buf][i].w);
            l.x = pkbf(bfres(av[buf][i].x), bfres(av[buf][i].y));
            l.y = pkbf(bfres(av[buf][i].z), bfres(av[buf][i].w));
            *(uint2*)&sAhi[(arow + i * 32) * LDK + ac4 * 4] = h;
            *(uint2*)&sAlo[(arow + i * 32) * LDK + ac4 * 4] = l;
        }
        *(uint2*)&sBhi[bn * LDK + bcc * 4] = bh[buf];
        *(uint2*)&sBlo[bn * LDK + bcc * 4] = bl[buf];
    };
    auto comp = [&]() {
#pragma unroll
        for (int ks = 0; ks < 2; ks++) {
            u32 ah[4], al[4], bh0v[4], bh1v[4], bl0v[4], bl1v[4];
            ldm_x4(uAh + ks * 32, ah);
            ldm_x4(uAl + ks * 32, al);
            ldm_x4(uBh + ks * 32, bh0v);
            ldm_x4(uBh + ks * 32 + 16, bh1v);
            ldm_x4(uBl + ks * 32, bl0v);
            ldm_x4(uBl + ks * 32 + 16, bl1v);
#pragma unroll
            for (int nb = 0; nb < 4; nb++) {
                mma16816(d[nb], ah, bh0v[nb], bh1v[nb]);
                mma16816(d[nb], al, bh0v[nb], bh1v[nb]);
                mma16816(d[nb], ah, bl0v[nb], bl1v[nb]);
            }
        }
    };

    ldg(ch0, 0);
    if (nch > 1) ldg(ch0 + 1, 1);
    for (int ch = 0; ch < nch; ch++) {
        __syncthreads();
        sts(ch & 1);
        if (ch + 2 < nch) ldg(ch0 + ch + 2, ch & 1);
        __syncthreads();
        comp();
    }

    int vlo = r0 + w * 16 + g;
    int vhi = vlo + 8;
    if (FIRST) {
        float blo = (vlo < VOUT) ? wg_b[vlo] : 0.f;
        float bhi_ = (vhi < VOUT) ? wg_b[vhi] : 0.f;
#pragma unroll
        for (int nb = 0; nb < 4; nb++) {
            int col = nb * 8 + q * 2;
            if (vlo < VOUT) {
                float2 o = { d[nb][0] + blo, d[nb][1] + blo };
                *(float2*)&g_wgout[(size_t)vlo * 32 + col] = o;
            }
            if (vhi < VOUT) {
                float2 o = { d[nb][2] + bhi_, d[nb][3] + bhi_ };
                *(float2*)&g_wgout[(size_t)vhi * 32 + col] = o;
            }
        }
    } else {
#pragma unroll
        for (int nb = 0; nb < 4; nb++) {
            int col = nb * 8 + q * 2;
            if (vlo < VOUT) {
                atomicAdd(&g_wgout[(size_t)vlo * 32 + col], d[nb][0]);
                atomicAdd(&g_wgout[(size_t)vlo * 32 + col + 1], d[nb][1]);
            }
            if (vhi < VOUT) {
                atomicAdd(&g_wgout[(size_t)vhi * 32 + col], d[nb][2]);
                atomicAdd(&g_wgout[(size_t)vhi * 32 + col + 1], d[nb][3]);
            }
        }
    }
}

// ---------------- K11a/b: log-sum-exp over VOUT (two-pass, unrolled) ----------------
__global__ void k11a_lse() {
    __shared__ float pm[8][32];
    __shared__ float ps[8][32];
    int w = threadIdx.x >> 5, lane = threadIdx.x & 31;
    int base = blockIdx.x * 1024 + w * 128;
    float mm[4] = {-INFINITY, -INFINITY, -INFINITY, -INFINITY};
#pragma unroll 8
    for (int i = 0; i < 128; i += 4) {
#pragma unroll
        for (int j = 0; j < 4; j++) {
            int v = base + i + j;
            if (v < VOUT) mm[j] = fmaxf(mm[j], g_wgout[(size_t)v * B + lane]);
        }
    }
    float m = fmaxf(fmaxf(mm[0], mm[1]), fmaxf(mm[2], mm[3]));
    float ss[4] = {0.f, 0.f, 0.f, 0.f};
#pragma unroll 8
    for (int i = 0; i < 128; i += 4) {
#pragma unroll
        for (int j = 0; j < 4; j++) {
            int v = base + i + j;
            if (v < VOUT) ss[j] += expf(g_wgout[(size_t)v * B + lane] - m);
        }
    }
    float s = (ss[0] + ss[1]) + (ss[2] + ss[3]);
    pm[w][lane] = m; ps[w][lane] = s;
    __syncthreads();
    if (w == 0) {
        float M = pm[0][lane], S = ps[0][lane];
#pragma unroll
        for (int i = 1; i < 8; i++) {
            float m2 = pm[i][lane], s2 = ps[i][lane];
            float nm = fmaxf(M, m2);
            S = S * expf(M - nm) + s2 * expf(m2 - nm);
            M = nm;
        }
        g_pmax[blockIdx.x * 32 + lane] = M;
        g_psum[blockIdx.x * 32 + lane] = S;
    }
}

__global__ void k11b_lse() {
    int b = threadIdx.x;
    float M = g_pmax[b], S = g_psum[b];
    for (int i = 1; i < NCHUNK; i++) {
        float m2 = g_pmax[i * 32 + b], s2 = g_psum[i * 32 + b];
        float nm = fmaxf(M, m2);
        S = S * expf(M - nm) + s2 * expf(m2 - nm);
        M = nm;
    }
    g_wlse[b] = M + logf(S);
}

// ---------------- K12: transpose + final vocab logits ----------------
__global__ void k12_out(float* __restrict__ d_out) {
    __shared__ float sm[32][33];
    int tx = threadIdx.x & 31, ty = threadIdx.x >> 5;
    int v0 = blockIdx.x * 32;
#pragma unroll
    for (int r = 0; r < 4; r++) {
        int row = r * 8 + ty;
        int v = v0 + row;
        if (v > VOUT - 1) v = VOUT - 1;
        sm[row][tx] = g_wgout[(size_t)v * B + tx];
    }
    __syncthreads();
#pragma unroll
    for (int r = 0; r < 4; r++) {
        int b = r * 8 + ty;
        int v = v0 + tx;
        if (v < VOUT)
            d_out[(size_t)b * LOGN + v] = g_sB[b] + sm[tx][b] - g_wlse[b];
    }
}

// ---------------- launch ----------------
extern "C" void kernel_launch(void* const* d_in, const int* in_sizes, int n_in,
                              void* d_out, int out_size) {
    const int*   n_input  = (const int*)d_in[0];
    const int*   t_input  = (const int*)d_in[1];
    const float* h0       = (const float*)d_in[2];
    const float* c0       = (const float*)d_in[3];
    const float* enc_out  = (const float*)d_in[4];
    const unsigned char* mask = (const unsigned char*)d_in[5];
    const float* h_parent = (const float*)d_in[6];
    const float* embN     = (const float*)d_in[7];
    const float* embT     = (const float*)d_in[8];
    const float* W_ih     = (const float*)d_in[9];
    const float* W_hh     = (const float*)d_in[10];
    const float* b_ih     = (const float*)d_in[11];
    const float* b_hh     = (const float*)d_in[12];
    const float* Wh_w     = (const float*)d_in[13];
    const float* Wh_b     = (const float*)d_in[14];
    const float* Wm_w     = (const float*)d_in[15];
    const float* Wm_b     = (const float*)d_in[16];
    const float* v_w      = (const float*)d_in[17];
    const float* v_b      = (const float*)d_in[18];
    const float* wg_w     = (const float*)d_in[19];
    const float* wg_b     = (const float*)d_in[20];
    const float* ws_w     = (const float*)d_in[21];
    const float* ws_b     = (const float*)d_in[22];
    float* out = (float*)d_out;

    float* gatesP; cudaGetSymbolAddress((void**)&gatesP, g_gates);
    float* qTP;    cudaGetSymbolAddress((void**)&qTP, g_qT);
    __nv_bfloat16* fhiP;  cudaGetSymbolAddress((void**)&fhiP, g_fhi);
    __nv_bfloat16* floP;  cudaGetSymbolAddress((void**)&floP, g_flo);
    __nv_bfloat16* ehiP;  cudaGetSymbolAddress((void**)&ehiP, g_ehi);
    __nv_bfloat16* eloP;  cudaGetSymbolAddress((void**)&eloP, g_elo);
    __nv_bfloat16* wmhiP; cudaGetSymbolAddress((void**)&wmhiP, g_wmhi);
    __nv_bfloat16* wmloP; cudaGetSymbolAddress((void**)&wmloP, g_wmlo);
    __nv_bfloat16* xbhiP; cudaGetSymbolAddress((void**)&xbhiP, g_xbhi);
    __nv_bfloat16* xbloP; cudaGetSymbolAddress((void**)&xbloP, g_xblo);
    __nv_bfloat16* hnhiP; cudaGetSymbolAddress((void**)&hnhiP, g_hnhi);
    __nv_bfloat16* hnloP; cudaGetSymbolAddress((void**)&hnloP, g_hnlo);

    // one-time side-stream + events (host handles only; no device allocations)
    static cudaStream_t s1 = nullptr;
    static cudaEvent_t evStart, evSplit, evK3, evA;
    if (!s1) {
        cudaStreamCreateWithFlags(&s1, cudaStreamNonBlocking);
        cudaEventCreateWithFlags(&evStart, cudaEventDisableTiming);
        cudaEventCreateWithFlags(&evSplit, cudaEventDisableTiming);
        cudaEventCreateWithFlags(&evK3, cudaEventDisableTiming);
        cudaEventCreateWithFlags(&evA, cudaEventDisableTiming);
    }
    cudaStream_t s0 = 0;   // legacy default stream

    // ---- fork: s1 does the enc/Wm bf16 splits while s0 runs the LSTM chain ----
    cudaEventRecord(evStart, s0);
    cudaStreamWaitEvent(s1, evStart, 0);
    k0_split<<<(B * L * H) / 256, 256, 0, s1>>>(enc_out, ehiP, eloP);
    k0_split<<<(H * H) / 256, 256, 0, s1>>>(Wm_w, wmhiP, wmloP);
    cudaEventRecord(evSplit, s1);

    k1_prep<<<B, 256, 0, s0>>>(n_input, t_input, h0, h_parent, embN, embT, v_b, b_ih, b_hh, Wh_b);
    kg_mma<<<dim3(G4 / 128, 4), 256, 0, s0>>>(W_ih, EIN, EIN / 32, W_hh, H,
                                              xbhiP, xbloP, EIN2, gatesP, 14);
    k3_lstm<<<(B * H) / 256, 256, 0, s0>>>(c0, out);
    cudaEventRecord(evK3, s0);

    // ---- s1: split h_new|h_parent features, then 2/3 of vocab GEMM (overlaps attention) ----
    cudaStreamWaitEvent(s1, evK3, 0);
    k9_split<<<dim3(2 * H / 256, B), 256, 0, s1>>>(fhiP, floP, H);
    k10_mma<true><<<(VOUT + 127) / 128, 256, 0, s1>>>(wg_w, wg_b, fhiP, floP, H / KC, 2 * H / KC);
    cudaEventRecord(evA, s1);

    // ---- s0: attention chain ----
    kg_mma<<<dim3(H / 128, 8), 256, 0, s0>>>(Wh_w, H, H / 32, (const float*)nullptr, 0,
                                             hnhiP, hnloP, H, qTP, 4);
    cudaStreamWaitEvent(s0, evSplit, 0);
    k5_mma<<<dim3(H / 64, B), 256, 0, s0>>>(ehiP, eloP, wmhiP, wmloP, Wm_b, v_w);
    k7_ctx<<<B, 256, 0, s0>>>(enc_out, mask);
    k8_s<<<B, 256, 0, s0>>>(ws_w, ws_b, out);
    k9_split<<<dim3(H / 256, B), 256, 0, s0>>>(fhiP, floP, 0);

    // ---- join: context third of vocab GEMM, then softmax + output ----
    cudaStreamWaitEvent(s0, evA, 0);
    k10_mma<false><<<(VOUT + 127) / 128, 256, 0, s0>>>(wg_w, wg_b, fhiP, floP, 0, H / KC);
    k11a_lse<<<NCHUNK, 256, 0, s0>>>();
    k11b_lse<<<1, 32, 0, s0>>>();
    k12_out<<<(VOUT + 31) / 32, 256, 0, s0>>>(out);
}

// round 14
// speedup vs baseline: 1.2798x; 1.2798x over previous
#include <cuda_runtime.h>
#include <cuda_bf16.h>
#include <math.h>

typedef unsigned long long ull;
typedef unsigned int u32;

#define DI __device__ __forceinline__

DI u32 pkbf(float a, float b){ u32 r; asm("cvt.rn.bf16x2.f32 %0, %1, %2;" : "=r"(r) : "f"(b), "f"(a)); return r; }  // mem order [a,b]
DI float bfres(float v){ __nv_bfloat16 h = __float2bfloat16(v); return v - __bfloat162float(h); }
DI u32 s2u(const void* p){ return (u32)__cvta_generic_to_shared(p); }

// warp mma: D[16x8] += A[16x16,row] * B[16x8,col], bf16 in, fp32 accum
DI void mma16816(float* d, const u32* a, u32 b0, u32 b1){
    asm volatile("mma.sync.aligned.m16n8k16.row.col.f32.bf16.bf16.f32 "
        "{%0,%1,%2,%3},{%4,%5,%6,%7},{%8,%9},{%0,%1,%2,%3};"
        : "+f"(d[0]), "+f"(d[1]), "+f"(d[2]), "+f"(d[3])
        : "r"(a[0]), "r"(a[1]), "r"(a[2]), "r"(a[3]), "r"(b0), "r"(b1));
}
DI void ldm_x4(u32 addr, u32* r){
    asm volatile("ldmatrix.sync.aligned.m8n8.x4.shared.b16 {%0,%1,%2,%3}, [%4];"
        : "=r"(r[0]), "=r"(r[1]), "=r"(r[2]), "=r"(r[3]) : "r"(addr));
}

static constexpr int B    = 32;
static constexpr int L    = 128;
static constexpr int H    = 1024;
static constexpr int EN   = 256;
static constexpr int ET   = 512;
static constexpr int EIN  = 768;
static constexpr int EIN2 = 1792;   // EIN + H
static constexpr int G4   = 4096;
static constexpr int VOUT = 50003;
static constexpr int LOGN = VOUT + L;
static constexpr int F3   = 3072;
static constexpr int NLOG = B * LOGN;
static constexpr int NCHUNK = 49;

// ---------------- scratch ----------------
__device__ __align__(16) float g_featT[F3 * B];
__device__ __align__(16) float g_gates[G4 * B];
__device__ __align__(16) float g_qT[H * B];
__device__ __align__(16) float g_scores[B * L];
__device__ float g_lse[B];
__device__ __align__(16) float g_context[B * H];
__device__ float g_sB[B];
__device__ __align__(16) float g_wgout[(VOUT + 64) * B];
__device__ float g_pmax[NCHUNK * 32];
__device__ float g_psum[NCHUNK * 32];
__device__ float g_wlse[B];
__device__ __align__(16) __nv_bfloat16 g_fhi[B * F3];
__device__ __align__(16) __nv_bfloat16 g_flo[B * F3];
__device__ __align__(16) __nv_bfloat16 g_ehi[B * L * H];
__device__ __align__(16) __nv_bfloat16 g_elo[B * L * H];
__device__ __align__(16) __nv_bfloat16 g_wmhi[H * H];
__device__ __align__(16) __nv_bfloat16 g_wmlo[H * H];
__device__ __align__(16) __nv_bfloat16 g_xbhi[B * EIN2];
__device__ __align__(16) __nv_bfloat16 g_xblo[B * EIN2];
__device__ __align__(16) __nv_bfloat16 g_hnhi[B * H];
__device__ __align__(16) __nv_bfloat16 g_hnlo[B * H];

// ---------------- K0: generic fp32 -> bf16 hi/lo split ----------------
__global__ void k0_split(const float* __restrict__ src, __nv_bfloat16* __restrict__ hi,
                         __nv_bfloat16* __restrict__ lo) {
    int i = blockIdx.x * 256 + threadIdx.x;
    float v = src[i];
    __nv_bfloat16 h = __float2bfloat16(v);
    hi[i] = h;
    lo[i] = __float2bfloat16(v - __bfloat162float(h));
}

// ---------------- K1: embeddings + staging + bias inits + x split ----------------
__global__ void k1_prep(const int* __restrict__ n_in, const int* __restrict__ t_in,
                        const float* __restrict__ h0, const float* __restrict__ h_parent,
                        const float* __restrict__ embN, const float* __restrict__ embT,
                        const float* __restrict__ v_b,
                        const float* __restrict__ b_ih, const float* __restrict__ b_hh,
                        const float* __restrict__ Wh_b) {
    int b = blockIdx.x;
    int t = threadIdx.x;
    int n  = n_in[b];
    int tt = t_in[b];
    for (int k = t; k < EIN; k += blockDim.x) {
        float v = (k < EN) ? embN[n * EN + k] : embT[(size_t)tt * ET + (k - EN)];
        __nv_bfloat16 h = __float2bfloat16(v);
        g_xbhi[b * EIN2 + k] = h;
        g_xblo[b * EIN2 + k] = __float2bfloat16(v - __bfloat162float(h));
    }
    for (int k = t; k < H; k += blockDim.x) {
        float v = h0[b * H + k];
        __nv_bfloat16 h = __float2bfloat16(v);
        g_xbhi[b * EIN2 + EIN + k] = h;
        g_xblo[b * EIN2 + EIN + k] = __float2bfloat16(v - __bfloat162float(h));
        g_featT[(2 * H + k) * B + b] = h_parent[b * H + k];
        g_qT[k * B + b] = Wh_b[k];
    }
    for (int j = t; j < G4; j += blockDim.x)
        g_gates[j * B + b] = b_ih[j] + b_hh[j];
    if (t < L) g_scores[b * L + t] = v_b[0];
}

// ---------------- KG: generic weight GEMM via mma (ldmatrix), split-K, atomic out ----------------
static constexpr int GLDK = 40;
__global__ void __launch_bounds__(256) kg_mma(const float* __restrict__ A1, int ldA1, int kb1,
                                              const float* __restrict__ A2, int ldA2,
                                              const __nv_bfloat16* __restrict__ bhi,
                                              const __nv_bfloat16* __restrict__ blo, int ldB,
                                              float* __restrict__ out, int chunksPerSplit) {
    __shared__ __align__(16) __nv_bfloat16 sAhi[128 * GLDK];
    __shared__ __align__(16) __nv_bfloat16 sAlo[128 * GLDK];
    __shared__ __align__(16) __nv_bfloat16 sBhi[32 * GLDK];
    __shared__ __align__(16) __nv_bfloat16 sBlo[32 * GLDK];
    int tid = threadIdx.x, w = tid >> 5, lane = tid & 31;
    int g = lane >> 2, q = lane & 3;
    int r0 = blockIdx.x * 128;
    int c0 = blockIdx.y * chunksPerSplit;
    int nkt = chunksPerSplit;

    float d[4][4];
#pragma unroll
    for (int nb = 0; nb < 4; nb++)
#pragma unroll
        for (int c = 0; c < 4; c++) d[nb][c] = 0.f;

    float4 av[2][4];
    uint2 bh[2], bl[2];
    int arow = tid >> 3, ac4 = tid & 7;
    int bn = tid >> 3, bcc = tid & 7;

    u32 uAh = s2u(sAhi) + ((w * 16 + (lane & 15)) * GLDK + (lane >> 4) * 8) * 2;
    u32 uAl = uAh + (s2u(sAlo) - s2u(sAhi));
    u32 uBh = s2u(sBhi) + lane * GLDK * 2;
    u32 uBl = uBh + (s2u(sBlo) - s2u(sBhi));

    auto ldg = [&](int ch, int buf) {
        const float* A; int ld_; int kk;
        if (ch < kb1) { A = A1; ld_ = ldA1; kk = ch * 32; }
        else          { A = A2; ld_ = ldA2; kk = (ch - kb1) * 32; }
#pragma unroll
        for (int i = 0; i < 4; i++)
            av[buf][i] = *(const float4*)&A[(size_t)(r0 + arow + i * 32) * ld_ + kk + 4 * ac4];
        int kb = ch * 32;
        bh[buf] = *(const uint2*)&bhi[bn * ldB + kb + bcc * 4];
        bl[buf] = *(const uint2*)&blo[bn * ldB + kb + bcc * 4];
    };
    auto sts = [&](int buf) {
#pragma unroll
        for (int i = 0; i < 4; i++) {
            uint2 h, l;
            h.x = pkbf(av[buf][i].x, av[buf][i].y);
            h.y = pkbf(av[buf][i].z, av[buf][i].w);
            l.x = pkbf(bfres(av[buf][i].x), bfres(av[buf][i].y));
            l.y = pkbf(bfres(av[buf][i].z), bfres(av[buf][i].w));
            *(uint2*)&sAhi[(arow + i * 32) * GLDK + ac4 * 4] = h;
            *(uint2*)&sAlo[(arow + i * 32) * GLDK + ac4 * 4] = l;
        }
        *(uint2*)&sBhi[bn * GLDK + bcc * 4] = bh[buf];
        *(uint2*)&sBlo[bn * GLDK + bcc * 4] = bl[buf];
    };
    auto comp = [&]() {
#pragma unroll
        for (int ks = 0; ks < 2; ks++) {
            u32 ah[4], al[4], bh0v[4], bh1v[4], bl0v[4], bl1v[4];
            ldm_x4(uAh + ks * 32, ah);
            ldm_x4(uAl + ks * 32, al);
            ldm_x4(uBh + ks * 32, bh0v);
            ldm_x4(uBh + ks * 32 + 16, bh1v);
            ldm_x4(uBl + ks * 32, bl0v);
            ldm_x4(uBl + ks * 32 + 16, bl1v);
#pragma unroll
            for (int nb = 0; nb < 4; nb++) {
                mma16816(d[nb], ah, bh0v[nb], bh1v[nb]);
                mma16816(d[nb], al, bh0v[nb], bh1v[nb]);
                mma16816(d[nb], ah, bl0v[nb], bl1v[nb]);
            }
        }
    };

    ldg(c0, 0);
    if (nkt > 1) ldg(c0 + 1, 1);
    for (int t = 0; t < nkt; t++) {
        __syncthreads();
        sts(t & 1);
        if (t + 2 < nkt) ldg(c0 + t + 2, t & 1);
        __syncthreads();
        comp();
    }

    int vlo = r0 + w * 16 + g;
    int vhi = vlo + 8;
#pragma unroll
    for (int nb = 0; nb < 4; nb++) {
        int col = nb * 8 + q * 2;
        atomicAdd(&out[(size_t)vlo * 32 + col], d[nb][0]);
        atomicAdd(&out[(size_t)vlo * 32 + col + 1], d[nb][1]);
        atomicAdd(&out[(size_t)vhi * 32 + col], d[nb][2]);
        atomicAdd(&out[(size_t)vhi * 32 + col + 1], d[nb][3]);
    }
}

// ---------------- K3: LSTM pointwise (+ h_new bf16 split) ----------------
__global__ void k3_lstm(const float* __restrict__ c0, float* __restrict__ d_out) {
    int idx = blockIdx.x * blockDim.x + threadIdx.x;
    int b = idx & 31, j = idx >> 5;
    float gi = g_gates[j * B + b];
    float gf = g_gates[(H + j) * B + b];
    float gg = g_gates[(2 * H + j) * B + b];
    float go = g_gates[(3 * H + j) * B + b];
    float cp = c0[b * H + j];
    float si = 1.f / (1.f + expf(-gi));
    float sf = 1.f / (1.f + expf(-gf));
    float so = 1.f / (1.f + expf(-go));
    float cn = sf * cp + si * tanhf(gg);
    float hn = so * tanhf(cn);
    g_featT[(H + j) * B + b] = hn;
    __nv_bfloat16 hh = __float2bfloat16(hn);
    g_hnhi[b * H + j] = hh;
    g_hnlo[b * H + j] = __float2bfloat16(hn - __bfloat162float(hh));
    d_out[NLOG + b * H + j] = hn;
    d_out[NLOG + B * H + b * H + j] = cn;
}

// ---------------- K5: attention GEMM via mma 3-pass + fused v*tanh (R12 form) ----------------
static constexpr int K5KC  = 32;
static constexpr int K5LDK = 40;

__global__ void __launch_bounds__(256) k5_mma(const __nv_bfloat16* __restrict__ ehi,
                                              const __nv_bfloat16* __restrict__ elo,
                                              const __nv_bfloat16* __restrict__ wmhi,
                                              const __nv_bfloat16* __restrict__ wmlo,
                                              const float* __restrict__ Wm_b,
                                              const float* __restrict__ v_w) {
    __shared__ __align__(16) __nv_bfloat16 sAhi[128 * K5LDK];
    __shared__ __align__(16) __nv_bfloat16 sAlo[128 * K5LDK];
    __shared__ __align__(16) __nv_bfloat16 sBhi[64 * K5LDK];
    __shared__ __align__(16) __nv_bfloat16 sBlo[64 * K5LDK];
    __shared__ float red[128];
    int tid = threadIdx.x, w = tid >> 5, lane = tid & 31;
    int g = lane >> 2, q = lane & 3;
    int n0 = blockIdx.x * 64;
    int by = blockIdx.y;
    const __nv_bfloat16* Ah = ehi + (size_t)by * L * H;
    const __nv_bfloat16* Al = elo + (size_t)by * L * H;

    float d[8][4];
#pragma unroll
    for (int nb = 0; nb < 8; nb++)
#pragma unroll
        for (int c = 0; c < 4; c++) d[nb][c] = 0.f;

    uint4 avh[2], avl[2], bvh, bvl;
    int arow = tid >> 2, ac8 = (tid & 3) * 8;
    int brow = tid >> 2, bc8 = (tid & 3) * 8;

    auto ldg = [&](int ch) {
        int k0 = ch * K5KC;
#pragma unroll
        for (int i = 0; i < 2; i++) {
            avh[i] = *(const uint4*)&Ah[(arow + i * 64) * H + k0 + ac8];
            avl[i] = *(const uint4*)&Al[(arow + i * 64) * H + k0 + ac8];
        }
        bvh = *(const uint4*)&wmhi[(size_t)(n0 + brow) * H + k0 + bc8];
        bvl = *(const uint4*)&wmlo[(size_t)(n0 + brow) * H + k0 + bc8];
    };
    auto sts = [&]() {
#pragma unroll
        for (int i = 0; i < 2; i++) {
            *(uint4*)&sAhi[(arow + i * 64) * K5LDK + ac8] = avh[i];
            *(uint4*)&sAlo[(arow + i * 64) * K5LDK + ac8] = avl[i];
        }
        *(uint4*)&sBhi[brow * K5LDK + bc8] = bvh;
        *(uint4*)&sBlo[brow * K5LDK + bc8] = bvl;
    };
    auto comp = [&]() {
#pragma unroll
        for (int ks = 0; ks < 2; ks++) {
            int kk = ks * 16 + q * 2;
            int ar = w * 16 + g;
            u32 ah[4], al[4];
            ah[0] = *(const u32*)&sAhi[ar * K5LDK + kk];
            ah[1] = *(const u32*)&sAhi[(ar + 8) * K5LDK + kk];
            ah[2] = *(const u32*)&sAhi[ar * K5LDK + kk + 8];
            ah[3] = *(const u32*)&sAhi[(ar + 8) * K5LDK + kk + 8];
            al[0] = *(const u32*)&sAlo[ar * K5LDK + kk];
            al[1] = *(const u32*)&sAlo[(ar + 8) * K5LDK + kk];
            al[2] = *(const u32*)&sAlo[ar * K5LDK + kk + 8];
            al[3] = *(const u32*)&sAlo[(ar + 8) * K5LDK + kk + 8];
#pragma unroll
            for (int nb = 0; nb < 8; nb++) {
                int bn = nb * 8 + g;
                u32 bh0 = *(const u32*)&sBhi[bn * K5LDK + kk];
                u32 bh1 = *(const u32*)&sBhi[bn * K5LDK + kk + 8];
                u32 bl0 = *(const u32*)&sBlo[bn * K5LDK + kk];
                u32 bl1 = *(const u32*)&sBlo[bn * K5LDK + kk + 8];
                mma16816(d[nb], ah, bh0, bh1);
                mma16816(d[nb], al, bh0, bh1);
                mma16816(d[nb], ah, bl0, bl1);
            }
        }
    };

    constexpr int NCH = H / K5KC;
    ldg(0);
    for (int ch = 0; ch < NCH; ch++) {
        __syncthreads();
        sts();
        if (ch + 1 < NCH) ldg(ch + 1);
        __syncthreads();
        comp();
    }

    float plo = 0.f, phi = 0.f;
#pragma unroll
    for (int nb = 0; nb < 8; nb++) {
        int col0 = n0 + nb * 8 + q * 2;
        int col1 = col0 + 1;
        float vw0 = v_w[col0], vw1 = v_w[col1];
        float mb0 = Wm_b[col0], mb1 = Wm_b[col1];
        float q0 = g_qT[col0 * B + by];
        float q1 = g_qT[col1 * B + by];
        plo += vw0 * tanhf(d[nb][0] + mb0 + q0) + vw1 * tanhf(d[nb][1] + mb1 + q1);
        phi += vw0 * tanhf(d[nb][2] + mb0 + q0) + vw1 * tanhf(d[nb][3] + mb1 + q1);
    }
    plo += __shfl_xor_sync(~0u, plo, 1);
    plo += __shfl_xor_sync(~0u, plo, 2);
    phi += __shfl_xor_sync(~0u, phi, 1);
    phi += __shfl_xor_sync(~0u, phi, 2);
    if (q == 0) {
        red[w * 16 + g] = plo;
        red[w * 16 + g + 8] = phi;
    }
    __syncthreads();
    if (tid < 128) atomicAdd(&g_scores[by * L + tid], red[tid]);
}

// ---------------- K7: softmax over L + context ----------------
__global__ void k7_ctx(const float* __restrict__ enc, const unsigned char* __restrict__ mask) {
    __shared__ float sc[128];
    __shared__ float redm[16];
    int b = blockIdx.x, t = threadIdx.x;
    if (t < 128) {
        float s = g_scores[b * L + t];
        if (mask[b * L + t]) s = -1e20f;
        sc[t] = s;
        g_scores[b * L + t] = s;
    }
    __syncthreads();
    float m = (t < 128) ? sc[t] : -INFINITY;
#pragma unroll
    for (int o = 16; o > 0; o >>= 1) m = fmaxf(m, __shfl_xor_sync(~0u, m, o));
    if ((t & 31) == 0) redm[t >> 5] = m;
    __syncthreads();
    if (t == 0) {
        float mm = redm[0];
        for (int w = 1; w < 8; w++) mm = fmaxf(mm, redm[w]);
        redm[0] = mm;
    }
    __syncthreads();
    float mx = redm[0];
    float e = (t < 128) ? expf(sc[t] - mx) : 0.f;
    float s = e;
#pragma unroll
    for (int o = 16; o > 0; o >>= 1) s += __shfl_xor_sync(~0u, s, o);
    if ((t & 31) == 0) redm[8 + (t >> 5)] = s;
    __syncthreads();
    if (t == 0) {
        float ss = 0.f;
        for (int w = 0; w < 8; w++) ss += redm[8 + w];
        redm[8] = ss;
    }
    __syncthreads();
    float sum = redm[8];
    if (t < 128) sc[t] = e / sum;
    if (t == 0) g_lse[b] = mx + logf(sum);
    __syncthreads();
    const float* E = enc + (size_t)b * L * H;
#pragma unroll
    for (int jj = 0; jj < 4; jj++) {
        int j = t + jj * 256;
        float a = 0.f;
#pragma unroll 4
        for (int l = 0; l < 128; l++) a += sc[l] * E[l * H + j];
        g_context[b * H + j] = a;
        g_featT[j * B + b] = a;
    }
}

// ---------------- K8: pointer switch + copy-logits ----------------
__global__ void k8_s(const float* __restrict__ ws_w, const float* __restrict__ ws_b,
                     float* __restrict__ d_out) {
    __shared__ float red[8];
    __shared__ float sh[2];
    int b = blockIdx.x, t = threadIdx.x;
    float a = 0.f;
    for (int j = t; j < H; j += 256) a += g_context[b * H + j] * ws_w[j];
    for (int j = t; j < H; j += 256) a += g_featT[(H + j) * B + b] * ws_w[H + j];
#pragma unroll
    for (int o = 16; o > 0; o >>= 1) a += __shfl_xor_sync(~0u, a, o);
    if ((t & 31) == 0) red[t >> 5] = a;
    __syncthreads();
    if (t == 0) {
        float zz = ws_b[0];
        for (int w = 0; w < 8; w++) zz += red[w];
        float s  = (zz >= 0.f) ? -log1pf(expf(-zz)) : zz - log1pf(expf(zz));
        float zm = -zz;
        float l1 = (zm >= 0.f) ? -log1pf(expf(-zm)) : zm - log1pf(expf(zm));
        l1 = fmaxf(l1, -41.446531673892822f);
        g_sB[b] = s;
        sh[0] = l1;
        sh[1] = g_lse[b];
    }
    __syncthreads();
    if (t < 128)
        d_out[(size_t)b * LOGN + VOUT + t] = sh[0] + g_scores[b * L + t] - sh[1];
}

// ---------------- K9: split featT region into bf16 hi/lo, [b][k] layout ----------------
__global__ void k9_split(__nv_bfloat16* __restrict__ fhi, __nv_bfloat16* __restrict__ flo,
                         int koff) {
    int b = blockIdx.y;
    int k = koff + blockIdx.x * 256 + threadIdx.x;
    float v = g_featT[k * B + b];
    __nv_bfloat16 h = __float2bfloat16(v);
    fhi[b * F3 + k] = h;
    flo[b * F3 + k] = __float2bfloat16(v - __bfloat162float(h));
}

// ---------------- K10: vocab GEMM via mma 3-pass, KC=64, chunk-range (R12 form) ----------------
static constexpr int KC   = 64;
static constexpr int LDK  = 72;

template<bool FIRST>
__global__ void __launch_bounds__(256) k10_mma(const float* __restrict__ wg_w,
                                               const float* __restrict__ wg_b,
                                               const __nv_bfloat16* __restrict__ fhi,
                                               const __nv_bfloat16* __restrict__ flo,
                                               int ch0, int nch) {
    __shared__ __align__(16) __nv_bfloat16 sAhi[128 * LDK];
    __shared__ __align__(16) __nv_bfloat16 sAlo[128 * LDK];
    __shared__ __align__(16) __nv_bfloat16 sBhi[32 * LDK];
    __shared__ __align__(16) __nv_bfloat16 sBlo[32 * LDK];
    int tid = threadIdx.x, w = tid >> 5, lane = tid & 31;
    int r0 = blockIdx.x * 128;
    int g = lane >> 2, q = lane & 3;

    float d[4][4];
#pragma unroll
    for (int nb = 0; nb < 4; nb++)
#pragma unroll
        for (int c = 0; c < 4; c++) d[nb][c] = 0.f;

    float4 av[8];
    uint2 bh[2], bl[2];
    int arow = tid >> 4, ac4 = tid & 15;
    int bn = tid >> 4, bcc = tid & 15;

    auto ldg = [&](int ch) {
        int k0 = ch * KC;
#pragma unroll
        for (int i = 0; i < 8; i++) {
            int rr = r0 + arow + i * 16;
            if (rr > VOUT - 1) rr = VOUT - 1;
            av[i] = *(const float4*)&wg_w[(size_t)rr * F3 + k0 + 4 * ac4];
        }
#pragma unroll
        for (int i = 0; i < 2; i++) {
            int n = bn + i * 16;
            bh[i] = *(const uint2*)&fhi[n * F3 + k0 + bcc * 4];
            bl[i] = *(const uint2*)&flo[n * F3 + k0 + bcc * 4];
        }
    };
    auto sts = [&]() {
#pragma unroll
        for (int i = 0; i < 8; i++) {
            uint2 h, l;
            h.x = pkbf(av[i].x, av[i].y);
            h.y = pkbf(av[i].z, av[i].w);
            l.x = pkbf(bfres(av[i].x), bfres(av[i].y));
            l.y = pkbf(bfres(av[i].z), bfres(av[i].w));
            *(uint2*)&sAhi[(arow + i * 16) * LDK + ac4 * 4] = h;
            *(uint2*)&sAlo[(arow + i * 16) * LDK + ac4 * 4] = l;
        }
#pragma unroll
        for (int i = 0; i < 2; i++) {
            int n = bn + i * 16;
            *(uint2*)&sBhi[n * LDK + bcc * 4] = bh[i];
            *(uint2*)&sBlo[n * LDK + bcc * 4] = bl[i];
        }
    };
    auto comp = [&]() {
#pragma unroll
        for (int ks = 0; ks < 4; ks++) {
            int kk = ks * 16 + q * 2;
            int ar = w * 16 + g;
            u32 ah[4], al[4];
            ah[0] = *(const u32*)&sAhi[ar * LDK + kk];
            ah[1] = *(const u32*)&sAhi[(ar + 8) * LDK + kk];
            ah[2] = *(const u32*)&sAhi[ar * LDK + kk + 8];
            ah[3] = *(const u32*)&sAhi[(ar + 8) * LDK + kk + 8];
            al[0] = *(const u32*)&sAlo[ar * LDK + kk];
            al[1] = *(const u32*)&sAlo[(ar + 8) * LDK + kk];
            al[2] = *(const u32*)&sAlo[ar * LDK + kk + 8];
            al[3] = *(const u32*)&sAlo[(ar + 8) * LDK + kk + 8];
#pragma unroll
            for (int nb = 0; nb < 4; nb++) {
                int bnn = nb * 8 + g;
                u32 bh0 = *(const u32*)&sBhi[bnn * LDK + kk];
                u32 bh1 = *(const u32*)&sBhi[bnn * LDK + kk + 8];
                u32 bl0 = *(const u32*)&sBlo[bnn * LDK + kk];
                u32 bl1 = *(const u32*)&sBlo[bnn * LDK + kk + 8];
                mma16816(d[nb], ah, bh0, bh1);
                mma16816(d[nb], al, bh0, bh1);
                mma16816(d[nb], ah, bl0, bl1);
            }
        }
    };

    ldg(ch0);
    for (int ch = 0; ch < nch; ch++) {
        __syncthreads();
        sts();
        if (ch + 1 < nch) ldg(ch0 + ch + 1);
        __syncthreads();
        comp();
    }

    int vlo = r0 + w * 16 + g;
    int vhi = vlo + 8;
    if (FIRST) {
        float blo = (vlo < VOUT) ? wg_b[vlo] : 0.f;
        float bhi_ = (vhi < VOUT) ? wg_b[vhi] : 0.f;
#pragma unroll
        for (int nb = 0; nb < 4; nb++) {
            int col = nb * 8 + q * 2;
            if (vlo < VOUT) {
                float2 o = { d[nb][0] + blo, d[nb][1] + blo };
                *(float2*)&g_wgout[(size_t)vlo * 32 + col] = o;
            }
            if (vhi < VOUT) {
                float2 o = { d[nb][2] + bhi_, d[nb][3] + bhi_ };
                *(float2*)&g_wgout[(size_t)vhi * 32 + col] = o;
            }
        }
    } else {
#pragma unroll
        for (int nb = 0; nb < 4; nb++) {
            int col = nb * 8 + q * 2;
            if (vlo < VOUT) {
                atomicAdd(&g_wgout[(size_t)vlo * 32 + col], d[nb][0]);
                atomicAdd(&g_wgout[(size_t)vlo * 32 + col + 1], d[nb][1]);
            }
            if (vhi < VOUT) {
                atomicAdd(&g_wgout[(size_t)vhi * 32 + col], d[nb][2]);
                atomicAdd(&g_wgout[(size_t)vhi * 32 + col + 1], d[nb][3]);
            }
        }
    }
}

// ---------------- K11a/b: log-sum-exp over VOUT (two-pass, unrolled) ----------------
__global__ void k11a_lse() {
    __shared__ float pm[8][32];
    __shared__ float ps[8][32];
    int w = threadIdx.x >> 5, lane = threadIdx.x & 31;
    int base = blockIdx.x * 1024 + w * 128;
    float mm[4] = {-INFINITY, -INFINITY, -INFINITY, -INFINITY};
#pragma unroll 8
    for (int i = 0; i < 128; i += 4) {
#pragma unroll
        for (int j = 0; j < 4; j++) {
            int v = base + i + j;
            if (v < VOUT) mm[j] = fmaxf(mm[j], g_wgout[(size_t)v * B + lane]);
        }
    }
    float m = fmaxf(fmaxf(mm[0], mm[1]), fmaxf(mm[2], mm[3]));
    float ss[4] = {0.f, 0.f, 0.f, 0.f};
#pragma unroll 8
    for (int i = 0; i < 128; i += 4) {
#pragma unroll
        for (int j = 0; j < 4; j++) {
            int v = base + i + j;
            if (v < VOUT) ss[j] += expf(g_wgout[(size_t)v * B + lane] - m);
        }
    }
    float s = (ss[0] + ss[1]) + (ss[2] + ss[3]);
    pm[w][lane] = m; ps[w][lane] = s;
    __syncthreads();
    if (w == 0) {
        float M = pm[0][lane], S = ps[0][lane];
#pragma unroll
        for (int i = 1; i < 8; i++) {
            float m2 = pm[i][lane], s2 = ps[i][lane];
            float nm = fmaxf(M, m2);
            S = S * expf(M - nm) + s2 * expf(m2 - nm);
            M = nm;
        }
        g_pmax[blockIdx.x * 32 + lane] = M;
        g_psum[blockIdx.x * 32 + lane] = S;
    }
}

__global__ void k11b_lse() {
    int b = threadIdx.x;
    float M = g_pmax[b], S = g_psum[b];
    for (int i = 1; i < NCHUNK; i++) {
        float m2 = g_pmax[i * 32 + b], s2 = g_psum[i * 32 + b];
        float nm = fmaxf(M, m2);
        S = S * expf(M - nm) + s2 * expf(m2 - nm);
        M = nm;
    }
    g_wlse[b] = M + logf(S);
}

// ---------------- K12: transpose + final vocab logits ----------------
__global__ void k12_out(float* __restrict__ d_out) {
    __shared__ float sm[32][33];
    int tx = threadIdx.x & 31, ty = threadIdx.x >> 5;
    int v0 = blockIdx.x * 32;
#pragma unroll
    for (int r = 0; r < 4; r++) {
        int row = r * 8 + ty;
        int v = v0 + row;
        if (v > VOUT - 1) v = VOUT - 1;
        sm[row][tx] = g_wgout[(size_t)v * B + tx];
    }
    __syncthreads();
#pragma unroll
    for (int r = 0; r < 4; r++) {
        int b = r * 8 + ty;
        int v = v0 + tx;
        if (v < VOUT)
            d_out[(size_t)b * LOGN + v] = g_sB[b] + sm[tx][b] - g_wlse[b];
    }
}

// ---------------- launch ----------------
extern "C" void kernel_launch(void* const* d_in, const int* in_sizes, int n_in,
                              void* d_out, int out_size) {
    const int*   n_input  = (const int*)d_in[0];
    const int*   t_input  = (const int*)d_in[1];
    const float* h0       = (const float*)d_in[2];
    const float* c0       = (const float*)d_in[3];
    const float* enc_out  = (const float*)d_in[4];
    const unsigned char* mask = (const unsigned char*)d_in[5];
    const float* h_parent = (const float*)d_in[6];
    const float* embN     = (const float*)d_in[7];
    const float* embT     = (const float*)d_in[8];
    const float* W_ih     = (const float*)d_in[9];
    const float* W_hh     = (const float*)d_in[10];
    const float* b_ih     = (const float*)d_in[11];
    const float* b_hh     = (const float*)d_in[12];
    const float* Wh_w     = (const float*)d_in[13];
    const float* Wh_b     = (const float*)d_in[14];
    const float* Wm_w     = (const float*)d_in[15];
    const float* Wm_b     = (const float*)d_in[16];
    const float* v_w      = (const float*)d_in[17];
    const float* v_b      = (const float*)d_in[18];
    const float* wg_w     = (const float*)d_in[19];
    const float* wg_b     = (const float*)d_in[20];
    const float* ws_w     = (const float*)d_in[21];
    const float* ws_b     = (const float*)d_in[22];
    float* out = (float*)d_out;

    float* gatesP; cudaGetSymbolAddress((void**)&gatesP, g_gates);
    float* qTP;    cudaGetSymbolAddress((void**)&qTP, g_qT);
    __nv_bfloat16* fhiP;  cudaGetSymbolAddress((void**)&fhiP, g_fhi);
    __nv_bfloat16* floP;  cudaGetSymbolAddress((void**)&floP, g_flo);
    __nv_bfloat16* ehiP;  cudaGetSymbolAddress((void**)&ehiP, g_ehi);
    __nv_bfloat16* eloP;  cudaGetSymbolAddress((void**)&eloP, g_elo);
    __nv_bfloat16* wmhiP; cudaGetSymbolAddress((void**)&wmhiP, g_wmhi);
    __nv_bfloat16* wmloP; cudaGetSymbolAddress((void**)&wmloP, g_wmlo);
    __nv_bfloat16* xbhiP; cudaGetSymbolAddress((void**)&xbhiP, g_xbhi);
    __nv_bfloat16* xbloP; cudaGetSymbolAddress((void**)&xbloP, g_xblo);
    __nv_bfloat16* hnhiP; cudaGetSymbolAddress((void**)&hnhiP, g_hnhi);
    __nv_bfloat16* hnloP; cudaGetSymbolAddress((void**)&hnloP, g_hnlo);

    // one-time side-stream + events (host handles only; no device allocations)
    static cudaStream_t s1 = nullptr;
    static cudaEvent_t evStart, evSplit, evK3, evA;
    if (!s1) {
        cudaStreamCreateWithFlags(&s1, cudaStreamNonBlocking);
        cudaEventCreateWithFlags(&evStart, cudaEventDisableTiming);
        cudaEventCreateWithFlags(&evSplit, cudaEventDisableTiming);
        cudaEventCreateWithFlags(&evK3, cudaEventDisableTiming);
        cudaEventCreateWithFlags(&evA, cudaEventDisableTiming);
    }
    cudaStream_t s0 = 0;   // legacy default stream

    // ---- fork: s1 does the enc/Wm bf16 splits while s0 runs the LSTM chain ----
    cudaEventRecord(evStart, s0);
    cudaStreamWaitEvent(s1, evStart, 0);
    k0_split<<<(B * L * H) / 256, 256, 0, s1>>>(enc_out, ehiP, eloP);
    k0_split<<<(H * H) / 256, 256, 0, s1>>>(Wm_w, wmhiP, wmloP);
    cudaEventRecord(evSplit, s1);

    k1_prep<<<B, 256, 0, s0>>>(n_input, t_input, h0, h_parent, embN, embT, v_b, b_ih, b_hh, Wh_b);
    // gates: 56 chunks, split-K x8 (7 chunks each)
    kg_mma<<<dim3(G4 / 128, 8), 256, 0, s0>>>(W_ih, EIN, EIN / 32, W_hh, H,
                                              xbhiP, xbloP, EIN2, gatesP, 7);
    k3_lstm<<<(B * H) / 256, 256, 0, s0>>>(c0, out);
    cudaEventRecord(evK3, s0);

    // ---- s1: split h_new|h_parent features, then 2/3 of vocab GEMM (overlaps attention) ----
    cudaStreamWaitEvent(s1, evK3, 0);
    k9_split<<<dim3(2 * H / 256, B), 256, 0, s1>>>(fhiP, floP, H);
    k10_mma<true><<<(VOUT + 127) / 128, 256, 0, s1>>>(wg_w, wg_b, fhiP, floP, H / KC, 2 * H / KC);
    cudaEventRecord(evA, s1);

    // ---- s0: attention chain ----
    // q: 32 chunks, split-K x8 (4 chunks each)
    kg_mma<<<dim3(H / 128, 8), 256, 0, s0>>>(Wh_w, H, H / 32, (const float*)nullptr, 0,
                                             hnhiP, hnloP, H, qTP, 4);
    cudaStreamWaitEvent(s0, evSplit, 0);
    k5_mma<<<dim3(H / 64, B), 256, 0, s0>>>(ehiP, eloP, wmhiP, wmloP, Wm_b, v_w);
    k7_ctx<<<B, 256, 0, s0>>>(enc_out, mask);
    k8_s<<<B, 256, 0, s0>>>(ws_w, ws_b, out);
    k9_split<<<dim3(H / 256, B), 256, 0, s0>>>(fhiP, floP, 0);

    // ---- join: context third of vocab GEMM, then softmax + output ----
    cudaStreamWaitEvent(s0, evA, 0);
    k10_mma<false><<<(VOUT + 127) / 128, 256, 0, s0>>>(wg_w, wg_b, fhiP, floP, 0, H / KC);
    k11a_lse<<<NCHUNK, 256, 0, s0>>>();
    k11b_lse<<<1, 32, 0, s0>>>();
    k12_out<<<(VOUT + 31) / 32, 256, 0, s0>>>(out);
}